// round 12
// baseline (speedup 1.0000x reference)
#include <cuda_runtime.h>
#include <math.h>

// ---------------------------------------------------------------------------
// DCRNN forward — single persistent kernel + software grid barrier.
//   * sparse CSR diffusion (S ~2% dense, 2S^2 ~13%) built on device once
//   * state in (N,B,F) layout: h IS the gconv h-input (no packing)
//   * candidate gconv reuses the gate gconv's diffusion of the x columns
//   * all 24 timesteps x 2 layers run inside ONE kernel; stage boundaries are
//     counting grid barriers (148 blocks, 1/SM guaranteed co-resident)
//   * FIX vs R11: encoder-input transpose in weight-GEMM A loader applies ONLY
//     to segment 0 (raw x); segments 2/4 read diffused g_X1x/g_X2x.
// ---------------------------------------------------------------------------

#define NN     325
#define BB     64
#define UU     64
#define TSTEPS 12
#define HSTEPS 12
#define RR     (NN*BB)      /* 20800 */
#define MST    (2*NN)       /* 650 */
#define LDK    336
#define JHH    (BB*UU)      /* 4096 */
#define CSRCAP (650*328)
#define GRD    148
#define NTHR   512

typedef unsigned long long ull;

// ------------------------- device scratch ----------------------------------
__device__ __align__(16) float g_L2 [MST*LDK];
__device__ __align__(16) float g_vals[CSRCAP];
__device__ __align__(16) int   g_cols[CSRCAP];
__device__ int   g_rp  [MST + 1];
__device__ int   g_cnt [MST];
__device__ __align__(16) float g_h0 [RR*UU];
__device__ __align__(16) float g_h1 [RR*UU];
__device__ __align__(16) float g_rh [RR*UU];
__device__ __align__(16) float g_u  [RR*UU];
__device__ __align__(16) float g_din[RR];
__device__ __align__(16) float g_X1x[NN*JHH];
__device__ __align__(16) float g_X2x[NN*JHH];
__device__ __align__(16) float g_X1h[NN*JHH];
__device__ __align__(16) float g_X2h[NN*JHH];
__device__ unsigned g_arrive;

// ------------------------- f32x2 helpers -----------------------------------
__device__ __forceinline__ ull pk2(float lo, float hi) {
    ull r; asm("mov.b64 %0, {%1,%2};" : "=l"(r) : "f"(lo), "f"(hi)); return r;
}
__device__ __forceinline__ void upk2(ull v, float &lo, float &hi) {
    asm("mov.b64 {%0,%1}, %2;" : "=f"(lo), "=f"(hi) : "l"(v));
}
__device__ __forceinline__ void fma2(ull &d, ull a, ull b) {
    asm("fma.rn.f32x2 %0, %1, %2, %0;" : "+l"(d) : "l"(a), "l"(b));
}

// ------------------------- grid barrier ------------------------------------
__device__ __forceinline__ void gridbar(unsigned &gen) {
    gen++;
    __syncthreads();
    if (threadIdx.x == 0) {
        __threadfence();                       // release my writes
        atomicAdd(&g_arrive, 1u);
        unsigned goal = gen * (unsigned)GRD;
        while (*((volatile unsigned*)&g_arrive) < goal) { }
        __threadfence();                       // invalidate L1 (acquire)
    }
    __syncthreads();
}

// ===================== prep kernels (once per launch) ======================
__global__ void k_lstack(const float* __restrict__ S) {
    int idx = blockIdx.x * blockDim.x + threadIdx.x;
    if (idx >= MST*LDK) return;
    int m = idx / LDK, n = idx % LDK;
    float v = 0.f;
    if (n < NN) {
        if (m < NN) v = S[m*NN + n];
        else {
            int mm = m - NN; float s = 0.f;
            for (int k = 0; k < NN; k++) s += S[mm*NN + k] * S[k*NN + n];
            v = 2.0f * s;
        }
    }
    g_L2[idx] = v;
}
__global__ void k_count() {
    int r = blockIdx.x * blockDim.x + threadIdx.x;
    if (r >= MST) return;
    int c = 0;
    for (int k = 0; k < NN; k++) c += (g_L2[r*LDK + k] != 0.f);
    g_cnt[r] = (c + 3) & ~3;
}
__global__ void k_scan() {            // single warp
    int lane = threadIdx.x;
    int run = 0;
    for (int base = 0; base < MST; base += 32) {
        int v = (base + lane < MST) ? g_cnt[base + lane] : 0;
        #pragma unroll
        for (int o = 1; o < 32; o <<= 1) {
            int n = __shfl_up_sync(0xffffffffu, v, o);
            if (lane >= o) v += n;
        }
        if (base + lane < MST) g_rp[base + lane + 1] = run + v;
        run += __shfl_sync(0xffffffffu, v, 31);
    }
    if (lane == 0) g_rp[0] = 0;
}
__global__ void k_fill() {            // warp per row, ballot compaction
    int w = (blockIdx.x * blockDim.x + threadIdx.x) >> 5;
    int lane = threadIdx.x & 31;
    if (w >= MST) return;
    int base = g_rp[w], cnt = 0;
    for (int k0 = 0; k0 < NN; k0 += 32) {
        int k = k0 + lane;
        float v = (k < NN) ? g_L2[w*LDK + k] : 0.f;
        unsigned m = __ballot_sync(0xffffffffu, v != 0.f);
        if (v != 0.f) {
            int pos = base + cnt + __popc(m & ((1u << lane) - 1u));
            g_vals[pos] = v; g_cols[pos] = k;
        }
        cnt += __popc(m);
    }
    for (int i = base + cnt + lane; i < g_rp[w+1]; i += 32) {
        g_vals[i] = 0.f; g_cols[i] = 0;
    }
}
__global__ void k_zero() {
    int i = blockIdx.x * blockDim.x + threadIdx.x;
    int st = gridDim.x * blockDim.x;
    for (int j = i; j < RR*UU; j += st) { g_h0[j] = 0.f; g_h1[j] = 0.f; }
    for (int j = i; j < RR;    j += st) g_din[j] = 0.f;
    if (i == 0) g_arrive = 0u;
}

// ===================== persistent-kernel stages ============================

// diffusion: CSR Lstack @ [x-part | h-part], 32-col j-tiles
__device__ void st_spmm(float* sm, bool encx, const float* xenc,
                        const float* xplain, int Jx, const float* hptr,
                        unsigned &gen)
{
    int nbx = Jx >> 5;
    int nT  = nbx + 128;
    for (int w = blockIdx.x; w < nT; w += GRD) {
        const float* Ain; int J, j0; float *O1, *O2; bool et;
        if (w < nbx) { Ain = xplain; J = Jx;  j0 = w << 5;        O1 = g_X1x; O2 = g_X2x; et = encx; }
        else         { Ain = hptr;   J = JHH; j0 = (w-nbx) << 5;  O1 = g_X1h; O2 = g_X2h; et = false; }
        __syncthreads();
        for (int idx = threadIdx.x; idx < NN*8; idx += NTHR) {
            int r = idx >> 3, c4 = idx & 7;
            float4 v;
            if (!et) v = *(const float4*)&Ain[(size_t)r*J + j0 + c4*4];
            else {
                int j = j0 + c4*4; int b = j >> 1;
                const float* p = xenc + (size_t)b*(2*NN) + r*2;
                float2 u0 = *(const float2*)p;
                float2 u1 = *(const float2*)(p + 2*NN);
                v = make_float4(u0.x, u0.y, u1.x, u1.y);
            }
            *(float4*)&sm[r*36 + c4*4] = v;
        }
        __syncthreads();
        int rg = threadIdx.x >> 3, cg = threadIdx.x & 7;
        int jg = j0 + cg*4;
        for (int r = rg; r < MST; r += 64) {
            int beg = g_rp[r], end = g_rp[r+1];
            ull a0 = 0, a1 = 0, a2 = 0, a3 = 0;
            for (int i = beg; i < end; i += 4) {
                int4   c4 = *(const int4*)  &g_cols[i];
                float4 v4 = *(const float4*)&g_vals[i];
                ulonglong2 b0 = *(const ulonglong2*)&sm[c4.x*36 + cg*4];
                ulonglong2 b1 = *(const ulonglong2*)&sm[c4.y*36 + cg*4];
                ulonglong2 b2 = *(const ulonglong2*)&sm[c4.z*36 + cg*4];
                ulonglong2 b3 = *(const ulonglong2*)&sm[c4.w*36 + cg*4];
                ull v0 = pk2(v4.x, v4.x), v1 = pk2(v4.y, v4.y);
                ull v2 = pk2(v4.z, v4.z), v3 = pk2(v4.w, v4.w);
                fma2(a0, v0, b0.x); fma2(a1, v0, b0.y);
                fma2(a2, v1, b1.x); fma2(a3, v1, b1.y);
                fma2(a0, v2, b2.x); fma2(a1, v2, b2.y);
                fma2(a2, v3, b3.x); fma2(a3, v3, b3.y);
            }
            float o0,o1,o2,o3,p0,p1,p2,p3;
            upk2(a0,o0,o1); upk2(a1,o2,o3); upk2(a2,p0,p1); upk2(a3,p2,p3);
            o0 += p0; o1 += p1; o2 += p2; o3 += p3;
            if (r < NN) {
                *(float4*)&O1[(size_t)r*J + jg] = make_float4(o0,o1,o2,o3);
            } else {
                int mm = r - NN;
                float4 x0 = *(const float4*)&sm[mm*36 + cg*4];
                *(float4*)&O2[(size_t)mm*J + jg] =
                    make_float4(o0 - x0.x, o1 - x0.y, o2 - x0.z, o3 - x0.w);
            }
        }
    }
    gridbar(gen);
}

// small-K (xF in {1,2}) A tile loader, optional encoder transpose (s==0 only)
__device__ __forceinline__ float smallA(const float* A, bool encT,
                                        const float* xenc, int row, int k, int K)
{
    if (k >= K) return 0.f;
    if (!encT) return A[(size_t)row*K + k];
    int n = row >> 6, b = row & 63;
    return xenc[((size_t)b*NN + n)*2 + k];
}

// gate GEMM: 64 rows x 128 cols tiles (325 tiles), sigmoid epilogue
__device__ void st_gate(float* sm, const float* W, const float* bias, int xF,
                        bool encx, const float* xenc, const float* xA,
                        const float* hArr, unsigned &gen)
{
    float* As = sm;                // [16][68]
    float* Bs = sm + 16*68;       // [16][128]
    const int F = xF + UU;
    const int ty = threadIdx.x >> 4, tx = threadIdx.x & 15;
    for (int tw = blockIdx.x; tw < 325; tw += GRD) {
        int r0 = tw << 6;
        ull acc[2][4];
        #pragma unroll
        for (int i = 0; i < 2; i++)
            #pragma unroll
            for (int j = 0; j < 4; j++) acc[i][j] = 0ULL;
        #pragma unroll 1
        for (int s = 0; s < 6; s++) {
            const float* A; int K, wr;
            switch (s) {
                case 0:  A = xA;     K = xF; wr = 0;        break;
                case 1:  A = hArr;   K = UU; wr = xF;       break;
                case 2:  A = g_X1x;  K = xF; wr = F;        break;
                case 3:  A = g_X1h;  K = UU; wr = F + xF;   break;
                case 4:  A = g_X2x;  K = xF; wr = 2*F;      break;
                default: A = g_X2h;  K = UU; wr = 2*F + xF; break;
            }
            bool encT = encx && (s == 0);      // transpose ONLY for raw x
            for (int k0 = 0; k0 < K; k0 += 16) {
                __syncthreads();
                if (K == UU) {
                    if (threadIdx.x < 256) {
                        int r = threadIdx.x >> 2, kq = threadIdx.x & 3;
                        float4 v = *(const float4*)&A[(size_t)(r0+r)*UU + k0 + kq*4];
                        As[(kq*4+0)*68 + r] = v.x; As[(kq*4+1)*68 + r] = v.y;
                        As[(kq*4+2)*68 + r] = v.z; As[(kq*4+3)*68 + r] = v.w;
                    }
                } else {
                    for (int idx = threadIdx.x; idx < 16*64; idx += NTHR) {
                        int r = idx >> 4, k = idx & 15;
                        As[k*68 + r] = smallA(A, encT, xenc, r0 + r, k, K);
                    }
                }
                {
                    int r = threadIdx.x >> 5, c4 = threadIdx.x & 31;
                    float4 v = {0.f,0.f,0.f,0.f};
                    if (k0 + r < K) v = *(const float4*)&W[(size_t)(wr+k0+r)*128 + c4*4];
                    *(float4*)&Bs[r*128 + c4*4] = v;
                }
                __syncthreads();
                #pragma unroll
                for (int k = 0; k < 16; k++) {
                    float2 a2 = *(const float2*)&As[k*68 + ty*2];
                    ulonglong2 q0 = *(const ulonglong2*)&Bs[k*128 + tx*8];
                    ulonglong2 q1 = *(const ulonglong2*)&Bs[k*128 + tx*8 + 4];
                    ull a0 = pk2(a2.x, a2.x), a1 = pk2(a2.y, a2.y);
                    fma2(acc[0][0],a0,q0.x); fma2(acc[0][1],a0,q0.y);
                    fma2(acc[0][2],a0,q1.x); fma2(acc[0][3],a0,q1.y);
                    fma2(acc[1][0],a1,q0.x); fma2(acc[1][1],a1,q0.y);
                    fma2(acc[1][2],a1,q1.x); fma2(acc[1][3],a1,q1.y);
                }
            }
        }
        #pragma unroll
        for (int i = 0; i < 2; i++) {
            int r = r0 + ty*2 + i;
            #pragma unroll
            for (int j = 0; j < 4; j++) {
                float lo, hi; upk2(acc[i][j], lo, hi);
                #pragma unroll
                for (int p = 0; p < 2; p++) {
                    int og = tx*8 + 2*j + p;
                    float v = (p ? hi : lo) + bias[og];
                    float sg = 1.0f / (1.0f + expf(-v));
                    if (og < UU) g_rh[(size_t)r*UU + og] = sg * hArr[(size_t)r*UU + og];
                    else         g_u [(size_t)r*UU + og - UU] = sg;
                }
            }
        }
    }
    gridbar(gen);
}

// candidate GEMM: 128 rows x 64 cols tiles (163 tiles), tanh + GRU update
__device__ void st_cand(float* sm, const float* W, const float* bias, int xF,
                        bool encx, const float* xenc, const float* xA,
                        float* hArr, unsigned &gen)
{
    float* As = sm;                // [16][132]
    float* Bs = sm + 16*132;      // [16][64]
    const int F = xF + UU;
    const int ty = threadIdx.x >> 4, tx = threadIdx.x & 15;
    for (int tw = blockIdx.x; tw < 163; tw += GRD) {
        int r0 = tw << 7;
        ull acc[4][2];
        #pragma unroll
        for (int i = 0; i < 4; i++) { acc[i][0] = 0ULL; acc[i][1] = 0ULL; }
        #pragma unroll 1
        for (int s = 0; s < 6; s++) {
            const float* A; int K, wr;
            switch (s) {
                case 0:  A = xA;     K = xF; wr = 0;        break;
                case 1:  A = g_rh;   K = UU; wr = xF;       break;
                case 2:  A = g_X1x;  K = xF; wr = F;        break;
                case 3:  A = g_X1h;  K = UU; wr = F + xF;   break;
                case 4:  A = g_X2x;  K = xF; wr = 2*F;      break;
                default: A = g_X2h;  K = UU; wr = 2*F + xF; break;
            }
            bool encT = encx && (s == 0);      // transpose ONLY for raw x
            for (int k0 = 0; k0 < K; k0 += 16) {
                __syncthreads();
                if (K == UU) {
                    int r = threadIdx.x >> 2, kq = threadIdx.x & 3;
                    float4 v = {0.f,0.f,0.f,0.f};
                    if (r0 + r < RR) v = *(const float4*)&A[(size_t)(r0+r)*UU + k0 + kq*4];
                    As[(kq*4+0)*132 + r] = v.x; As[(kq*4+1)*132 + r] = v.y;
                    As[(kq*4+2)*132 + r] = v.z; As[(kq*4+3)*132 + r] = v.w;
                } else {
                    for (int idx = threadIdx.x; idx < 16*128; idx += NTHR) {
                        int r = idx >> 4, k = idx & 15;
                        As[k*132 + r] = (r0 + r < RR) ? smallA(A, encT, xenc, r0 + r, k, K) : 0.f;
                    }
                }
                if (threadIdx.x < 256) {
                    int r = threadIdx.x >> 4, c4 = threadIdx.x & 15;
                    float4 v = {0.f,0.f,0.f,0.f};
                    if (k0 + r < K) v = *(const float4*)&W[(size_t)(wr+k0+r)*64 + c4*4];
                    *(float4*)&Bs[r*64 + c4*4] = v;
                }
                __syncthreads();
                #pragma unroll
                for (int k = 0; k < 16; k++) {
                    float4 a4 = *(const float4*)&As[k*132 + ty*4];
                    ulonglong2 q = *(const ulonglong2*)&Bs[k*64 + tx*4];
                    ull a0 = pk2(a4.x,a4.x), a1 = pk2(a4.y,a4.y);
                    ull a2 = pk2(a4.z,a4.z), a3 = pk2(a4.w,a4.w);
                    fma2(acc[0][0],a0,q.x); fma2(acc[0][1],a0,q.y);
                    fma2(acc[1][0],a1,q.x); fma2(acc[1][1],a1,q.y);
                    fma2(acc[2][0],a2,q.x); fma2(acc[2][1],a2,q.y);
                    fma2(acc[3][0],a3,q.x); fma2(acc[3][1],a3,q.y);
                }
            }
        }
        #pragma unroll
        for (int i = 0; i < 4; i++) {
            int r = r0 + ty*4 + i;
            if (r >= RR) continue;
            #pragma unroll
            for (int j = 0; j < 2; j++) {
                float lo, hi; upk2(acc[i][j], lo, hi);
                #pragma unroll
                for (int p = 0; p < 2; p++) {
                    int og = tx*4 + 2*j + p;
                    float v = (p ? hi : lo) + bias[og];
                    float c = tanhf(v);
                    size_t idx = (size_t)r*UU + og;
                    float u = g_u[idx];
                    hArr[idx] = u * hArr[idx] + (1.0f - u) * c;
                }
            }
        }
    }
    gridbar(gen);
}

__device__ void st_proj(const float* pW, const float* pb, float* outp, unsigned &gen) {
    int gw = (blockIdx.x * NTHR + threadIdx.x) >> 5;
    int lane = threadIdx.x & 31;
    float w0 = pW[lane], w1 = pW[lane + 32], b0 = pb[0];
    for (int r = gw; r < RR; r += (GRD*NTHR) >> 5) {
        float s = g_h1[(size_t)r*UU + lane] * w0 + g_h1[(size_t)r*UU + 32 + lane] * w1;
        #pragma unroll
        for (int o = 16; o; o >>= 1) s += __shfl_down_sync(0xffffffffu, s, o);
        if (lane == 0) {
            float v = s + b0;
            int n = r >> 6, b = r & 63;
            outp[b*NN + n] = v;
            g_din[r] = v;
        }
    }
    gridbar(gen);
}

__device__ void cell(float* sm, unsigned &gen, int xF, bool encx,
                     const float* xenc, const float* xplain, float* hArr,
                     const float* gW, const float* gb,
                     const float* cW, const float* cb)
{
    st_spmm(sm, encx, xenc, xplain, BB*xF, hArr, gen);       // diffuse [x|h]
    st_gate(sm, gW, gb, xF, encx, xenc, xplain, hArr, gen);  // r,u ; rh=r*h
    st_spmm(sm, false, nullptr, nullptr, 0, g_rh, gen);      // diffuse r*h
    st_cand(sm, cW, cb, xF, encx, xenc, xplain, hArr, gen);  // h update
}

struct KP {
    const float* inp;
    const float* w[16];
    const float* pW; const float* pb;
    float* out;
};

__global__ __launch_bounds__(NTHR, 1) void k_run(KP P) {
    __shared__ __align__(16) float sm[NN*36];   // 46.8 KB, unioned per stage
    unsigned gen = 0;
    for (int t = 0; t < TSTEPS; t++) {
        const float* xt = P.inp + (size_t)t * BB * NN * 2;
        cell(sm, gen, 2,  true,  xt,      nullptr, g_h0, P.w[0],  P.w[1],  P.w[2],  P.w[3]);
        cell(sm, gen, 64, false, nullptr, g_h0,    g_h1, P.w[4],  P.w[5],  P.w[6],  P.w[7]);
    }
    for (int t = 0; t < HSTEPS; t++) {
        cell(sm, gen, 1,  false, nullptr, g_din,   g_h0, P.w[8],  P.w[9],  P.w[10], P.w[11]);
        cell(sm, gen, 64, false, nullptr, g_h0,    g_h1, P.w[12], P.w[13], P.w[14], P.w[15]);
        st_proj(P.pW, P.pb, P.out + (size_t)t * BB * NN, gen);
    }
}

// ------------------------------- host side ---------------------------------
extern "C" void kernel_launch(void* const* d_in, const int* in_sizes, int n_in,
                              void* d_out, int out_size) {
    KP P;
    P.inp = (const float*)d_in[0];
    const float* support = (const float*)d_in[1];
    for (int i = 0; i < 16; i++) P.w[i] = (const float*)d_in[2 + i];
    P.pW  = (const float*)d_in[18];
    P.pb  = (const float*)d_in[19];
    P.out = (float*)d_out;

    k_lstack<<<(MST*LDK + 255) / 256, 256>>>(support);
    k_count <<<(MST + 255) / 256, 256>>>();
    k_scan  <<<1, 32>>>();
    k_fill  <<<(MST*32 + 255) / 256, 256>>>();
    k_zero  <<<592, 256>>>();
    k_run   <<<GRD, NTHR>>>(P);
}